// round 3
// baseline (speedup 1.0000x reference)
#include <cuda_runtime.h>
#include <cuda_bf16.h>

#define NN 50000
#define NE 800000
#define DIN 96
#define HID 128
#define NG 256
#define NCAT 256
#define K1 288      // 3 * 96  (layer-1 split-K)
#define K2 384      // 3 * 128 (layer-2 split-K)
#define NBLKM ((NN + 127) / 128)   // 391

// ---------------- scratch (__device__ globals; allocation-free) ----------------
__device__ __align__(16) int   g_deg[NN];
__device__ __align__(16) int   g_off[NN + 1];
__device__ __align__(16) int   g_cur[NN];
__device__ __align__(16) int   g_esrc[NE];
__device__ __align__(16) float g_ew[NE];
__device__ __align__(16) float g_Y[(size_t)NN * NCAT];   // GEMM out (both layers)
__device__ __align__(16) float g_h2[(size_t)NN * HID];
__device__ __align__(16) __nv_bfloat16 g_A1[(size_t)NN * K1];  // [Ah|Ah|Al] of x
__device__ __align__(16) __nv_bfloat16 g_A2[(size_t)NN * K2];  // [Ah|Ah|Al] of h1
__device__ __align__(16) __nv_bfloat16 g_B1[NCAT * K1];        // [Bh|Bl|Bh] layer1
__device__ __align__(16) __nv_bfloat16 g_B2[NCAT * K2];        // [Bh|Bl|Bh] layer2

// ---------------- helpers ----------------
__device__ __forceinline__ unsigned smem_u32(const void* p) {
    unsigned a;
    asm("{ .reg .u64 t; cvta.to.shared.u64 t, %1; cvt.u32.u64 %0, t; }" : "=r"(a) : "l"(p));
    return a;
}

__device__ __forceinline__ void ldsm_x4(unsigned* r, unsigned addr) {
    asm volatile("ldmatrix.sync.aligned.m8n8.x4.shared.b16 {%0,%1,%2,%3}, [%4];"
                 : "=r"(r[0]), "=r"(r[1]), "=r"(r[2]), "=r"(r[3]) : "r"(addr));
}

__device__ __forceinline__ void mma16816(float* c, const unsigned* a, const unsigned* b) {
    asm volatile(
        "mma.sync.aligned.m16n8k16.row.col.f32.bf16.bf16.f32 "
        "{%0,%1,%2,%3}, {%4,%5,%6,%7}, {%8,%9}, {%0,%1,%2,%3};"
        : "+f"(c[0]), "+f"(c[1]), "+f"(c[2]), "+f"(c[3])
        : "r"(a[0]), "r"(a[1]), "r"(a[2]), "r"(a[3]), "r"(b[0]), "r"(b[1]));
}

__device__ __forceinline__ void cp16(unsigned saddr, const void* gaddr, bool valid) {
    asm volatile("cp.async.cg.shared.global [%0], [%1], 16, %2;"
                 :: "r"(saddr), "l"(gaddr), "r"(valid ? 16u : 0u) : "memory");
}

__device__ __forceinline__ void split2(float v, __nv_bfloat16& h, __nv_bfloat16& l) {
    h = __float2bfloat16(v);
    l = __float2bfloat16(v - __bfloat162float(h));
}

// ---------------- CSR build ----------------
__global__ void k_zero_deg() {
    int i = blockIdx.x * blockDim.x + threadIdx.x;
    if (i < NN) g_deg[i] = 0;
}

__global__ void k_count(const int* __restrict__ ei) {
    int e = blockIdx.x * blockDim.x + threadIdx.x;
    if (e < NE) atomicAdd(&g_deg[ei[NE + e]], 1);
}

__global__ void k_scan() {
    __shared__ int wsum[32];
    const int tid = threadIdx.x;
    const int CH = (NN + 1023) / 1024;
    const int base = tid * CH;
    int s = 0;
    for (int i = 0; i < CH; i++) {
        int idx = base + i;
        if (idx < NN) s += g_deg[idx];
    }
    int lane = tid & 31, w = tid >> 5;
    int v = s;
    #pragma unroll
    for (int o = 1; o < 32; o <<= 1) {
        int n = __shfl_up_sync(0xffffffffu, v, o);
        if (lane >= o) v += n;
    }
    if (lane == 31) wsum[w] = v;
    __syncthreads();
    if (w == 0) {
        int x = wsum[lane];
        #pragma unroll
        for (int o = 1; o < 32; o <<= 1) {
            int n = __shfl_up_sync(0xffffffffu, x, o);
            if (lane >= o) x += n;
        }
        wsum[lane] = x;
    }
    __syncthreads();
    int excl = v - s + (w > 0 ? wsum[w - 1] : 0);
    int run = excl;
    for (int i = 0; i < CH; i++) {
        int idx = base + i;
        if (idx < NN) {
            g_off[idx] = run;
            g_cur[idx] = run;
            run += g_deg[idx];
        }
    }
    if (tid == 1023) g_off[NN] = run;
}

__global__ void k_scatter(const int* __restrict__ ei, const float* __restrict__ ea) {
    int e = blockIdx.x * blockDim.x + threadIdx.x;
    if (e < NE) {
        int d = ei[NE + e];
        int p = atomicAdd(&g_cur[d], 1);
        g_esrc[p] = ei[e];
        g_ew[p]   = ea[e];
    }
}

// ---------------- conversions ----------------
// x [NN,96] fp32 -> g_A1 [NN,288] = [Ah(96) | Ah(96) | Al(96)]
__global__ void k_conv_x(const float* __restrict__ x) {
    int t = blockIdx.x * blockDim.x + threadIdx.x;
    if (t >= NN * 24) return;
    int row = t / 24;
    int c4 = (t % 24) * 4;
    float4 v = *(const float4*)(x + (size_t)row * DIN + c4);
    __nv_bfloat16 h[4], l[4];
    split2(v.x, h[0], l[0]); split2(v.y, h[1], l[1]);
    split2(v.z, h[2], l[2]); split2(v.w, h[3], l[3]);
    __nv_bfloat16* dst = g_A1 + (size_t)row * K1;
    *(uint2*)(dst + c4)           = *(uint2*)h;
    *(uint2*)(dst + DIN + c4)     = *(uint2*)h;
    *(uint2*)(dst + 2 * DIN + c4) = *(uint2*)l;
}

// weights -> B' [n][3K] = [Bh | Bl | Bh] (row n = output channel, K-contig)
__global__ void k_prep_w(const float* __restrict__ Wr1, const float* __restrict__ Wro1,
                         const float* __restrict__ Wr3, const float* __restrict__ Wro3) {
    int idx = blockIdx.x * blockDim.x + threadIdx.x;
    const int n1 = NCAT * DIN;
    const int n2 = NCAT * HID;
    if (idx < n1) {
        int n = idx / DIN, k = idx % DIN;
        float v = (n < HID) ? Wr1[n * DIN + k] : Wro1[(n - HID) * DIN + k];
        __nv_bfloat16 h, l;
        split2(v, h, l);
        __nv_bfloat16* dst = g_B1 + (size_t)n * K1;
        dst[k] = h; dst[DIN + k] = l; dst[2 * DIN + k] = h;
    } else if (idx < n1 + n2) {
        int t = idx - n1;
        int n = t / HID, k = t % HID;
        float v = (n < HID) ? Wr3[n * HID + k] : Wro3[(n - HID) * HID + k];
        __nv_bfloat16 h, l;
        split2(v, h, l);
        __nv_bfloat16* dst = g_B2 + (size_t)n * K2;
        dst[k] = h; dst[HID + k] = l; dst[2 * HID + k] = h;
    }
}

// ---------------- tensor-core GEMM (mma.sync bf16, fp32 accum) -----------------
// g_Y[128 rows][128 cols-of-256] = A'[128 x KT] @ B'^T, B' is [256][KT] K-contig.
// CTA: 256 thr, 8 warps (4M x 2N), warp tile 32x64, BK=32, cp.async double-buffer.
#define SSTRIDE 40   // bf16 elems per smem row (32 data + 8 pad) -> conflict-free
#define SBUFB (128 * SSTRIDE * 2)  // bytes per buffer per operand = 10240

template <int KT>
__global__ __launch_bounds__(256) void k_gemm(const __nv_bfloat16* __restrict__ A,
                                              const __nv_bfloat16* __restrict__ B) {
    __shared__ __nv_bfloat16 As[2][128 * SSTRIDE];
    __shared__ __nv_bfloat16 Bs[2][128 * SSTRIDE];
    const int tid = threadIdx.x;
    const int lane = tid & 31;
    const int w = tid >> 5;
    const int wm = w & 3, wn = w >> 2;
    const int m0 = blockIdx.y * 128;
    const int n0 = blockIdx.x * 128;
    const unsigned asB = smem_u32(As);
    const unsigned bsB = smem_u32(Bs);

    float acc[2][8][4];
    #pragma unroll
    for (int i = 0; i < 2; i++)
        #pragma unroll
        for (int j = 0; j < 8; j++)
            #pragma unroll
            for (int q = 0; q < 4; q++) acc[i][j][q] = 0.f;

    const int NI = KT / 32;

    auto prefetch = [&](int kc, int buf) {
        #pragma unroll
        for (int i = 0; i < 2; i++) {
            int idx = tid + 256 * i;
            int r = idx >> 2;
            int cg = (idx & 3) * 8;
            unsigned soff = (unsigned)(r * SSTRIDE + cg) * 2u;
            bool okA = (m0 + r) < NN;
            cp16(asB + buf * SBUFB + soff,
                 A + (size_t)(m0 + r) * KT + kc + cg, okA);
            cp16(bsB + buf * SBUFB + soff,
                 B + (size_t)(n0 + r) * KT + kc + cg, true);
        }
    };

    prefetch(0, 0);
    asm volatile("cp.async.commit_group;" ::: "memory");

    int buf = 0;
    for (int it = 0; it < NI; it++) {
        asm volatile("cp.async.wait_group 0;" ::: "memory");
        __syncthreads();
        if (it + 1 < NI) {
            prefetch((it + 1) * 32, buf ^ 1);
            asm volatile("cp.async.commit_group;" ::: "memory");
        }
        const unsigned aBase = asB + buf * SBUFB;
        const unsigned bBase = bsB + buf * SBUFB;
        const int q = lane >> 3, rr = lane & 7;
        #pragma unroll
        for (int ks = 0; ks < 32; ks += 16) {
            unsigned af[2][4];
            #pragma unroll
            for (int mt = 0; mt < 2; mt++) {
                int row = wm * 32 + mt * 16 + (q & 1) * 8 + rr;
                int col = ks + (q >> 1) * 8;
                ldsm_x4(af[mt], aBase + (unsigned)(row * SSTRIDE + col) * 2u);
            }
            unsigned bfr[8][2];
            #pragma unroll
            for (int np = 0; np < 4; np++) {
                int nb = wn * 64 + np * 16 + (q >> 1) * 8 + rr;
                int col = ks + (q & 1) * 8;
                unsigned t4[4];
                ldsm_x4(t4, bBase + (unsigned)(nb * SSTRIDE + col) * 2u);
                bfr[2 * np][0] = t4[0];
                bfr[2 * np][1] = t4[1];
                bfr[2 * np + 1][0] = t4[2];
                bfr[2 * np + 1][1] = t4[3];
            }
            #pragma unroll
            for (int mt = 0; mt < 2; mt++)
                #pragma unroll
                for (int nt = 0; nt < 8; nt++)
                    mma16816(acc[mt][nt], af[mt], bfr[nt]);
        }
        buf ^= 1;
    }

    // epilogue
    #pragma unroll
    for (int mt = 0; mt < 2; mt++) {
        int row = m0 + wm * 32 + mt * 16 + (lane >> 2);
        #pragma unroll
        for (int nt = 0; nt < 8; nt++) {
            int col = n0 + wn * 64 + nt * 8 + (lane & 3) * 2;
            if (row < NN) {
                float2 v0 = make_float2(acc[mt][nt][0], acc[mt][nt][1]);
                *(float2*)(g_Y + (size_t)row * NCAT + col) = v0;
            }
            if (row + 8 < NN) {
                float2 v1 = make_float2(acc[mt][nt][2], acc[mt][nt][3]);
                *(float2*)(g_Y + (size_t)(row + 8) * NCAT + col) = v1;
            }
        }
    }
}

// ---------------- edge aggregation (warp/node CSR gather, no atomics) ----------
// layer==1: bias+relu -> g_A2 [node][384] = [Ah|Ah|Al] of h1
// layer==2: bias      -> g_h2 fp32
__global__ void k_agg(const float* __restrict__ bias, int layer) {
    int node = (blockIdx.x * blockDim.x + threadIdx.x) >> 5;
    if (node >= NN) return;
    int lane = threadIdx.x & 31;
    int beg = g_off[node], end = g_off[node + 1];
    float ax = 0.f, ay = 0.f, az = 0.f, aw = 0.f;
    for (int e = beg; e < end; e++) {
        int s = g_esrc[e];
        float wt = g_ew[e];
        float4 v = *(const float4*)(g_Y + (size_t)s * NCAT + 4 * lane);
        ax = fmaf(v.x, wt, ax);
        ay = fmaf(v.y, wt, ay);
        az = fmaf(v.z, wt, az);
        aw = fmaf(v.w, wt, aw);
    }
    float4 r = *(const float4*)(g_Y + (size_t)node * NCAT + HID + 4 * lane);
    float4 b = *(const float4*)(bias + 4 * lane);
    ax += r.x + b.x;
    ay += r.y + b.y;
    az += r.z + b.z;
    aw += r.w + b.w;
    if (layer == 1) {
        ax = fmaxf(ax, 0.f); ay = fmaxf(ay, 0.f);
        az = fmaxf(az, 0.f); aw = fmaxf(aw, 0.f);
        __nv_bfloat16 h[4], l[4];
        split2(ax, h[0], l[0]); split2(ay, h[1], l[1]);
        split2(az, h[2], l[2]); split2(aw, h[3], l[3]);
        __nv_bfloat16* dst = g_A2 + (size_t)node * K2;
        int k = 4 * lane;
        *(uint2*)(dst + k)           = *(uint2*)h;
        *(uint2*)(dst + HID + k)     = *(uint2*)h;
        *(uint2*)(dst + 2 * HID + k) = *(uint2*)l;
    } else {
        *(float4*)(g_h2 + (size_t)node * HID + 4 * lane) = make_float4(ax, ay, az, aw);
    }
}

// ---------------- pooling + head ----------------
__global__ void k_pool(const int* __restrict__ batch, const float* __restrict__ Wl,
                       const float* __restrict__ bl, float* __restrict__ out) {
    int g = blockIdx.x;
    int c = threadIdx.x;
    int lo = 0, hi = NN;
    while (lo < hi) {
        int m = (lo + hi) >> 1;
        if (batch[m] < g) lo = m + 1; else hi = m;
    }
    int l = lo, h = NN;
    while (l < h) {
        int m = (l + h) >> 1;
        if (batch[m] < g + 1) l = m + 1; else h = m;
    }
    int cnt = l - lo;
    float s = 0.f;
    for (int i = lo; i < l; i++) s += g_h2[(size_t)i * HID + c];
    float p = s / fmaxf((float)cnt, 1.f);
    float v = p * Wl[c];
    __shared__ float red[128];
    red[c] = v;
    __syncthreads();
    for (int st = 64; st > 0; st >>= 1) {
        if (c < st) red[c] += red[c + st];
        __syncthreads();
    }
    if (c == 0) out[g] = fmaxf(red[0] + bl[0], 0.f);
}

// ---------------- launch ----------------
extern "C" void kernel_launch(void* const* d_in, const int* in_sizes, int n_in,
                              void* d_out, int out_size) {
    const float* x     = (const float*)d_in[0];
    const int*   ei    = (const int*)d_in[1];
    const int*   batch = (const int*)d_in[2];
    const float* ea    = (const float*)d_in[3];
    const float* Wr1   = (const float*)d_in[4];
    const float* b1    = (const float*)d_in[5];
    const float* Wro1  = (const float*)d_in[6];
    const float* Wr3   = (const float*)d_in[7];
    const float* b3    = (const float*)d_in[8];
    const float* Wro3  = (const float*)d_in[9];
    const float* Wl    = (const float*)d_in[10];
    const float* bl    = (const float*)d_in[11];
    float* out = (float*)d_out;

    k_zero_deg<<<(NN + 255) / 256, 256>>>();
    k_count<<<(NE + 255) / 256, 256>>>(ei);
    k_scan<<<1, 1024>>>();
    k_scatter<<<(NE + 255) / 256, 256>>>(ei, ea);
    k_conv_x<<<(NN * 24 + 255) / 256, 256>>>(x);
    k_prep_w<<<(NCAT * (DIN + HID) + 255) / 256, 256>>>(Wr1, Wro1, Wr3, Wro3);

    dim3 ggrid(2, NBLKM);
    // layer 1
    k_gemm<K1><<<ggrid, 256>>>(g_A1, g_B1);
    k_agg<<<(NN * 32 + 255) / 256, 256>>>(b1, 1);
    // layer 2
    k_gemm<K2><<<ggrid, 256>>>(g_A2, g_B2);
    k_agg<<<(NN * 32 + 255) / 256, 256>>>(b3, 2);
    // pool + head
    k_pool<<<NG, 128>>>(batch, Wl, bl, out);
}

// round 4
// speedup vs baseline: 8.3954x; 8.3954x over previous
#include <cuda_runtime.h>
#include <cuda_bf16.h>

#define NN 50000
#define NE 800000
#define DIN 96
#define HID 128
#define NG 256
#define NCAT 256   // [W_rel | W_root] concatenated output width

// ---------------- scratch (__device__ globals; allocation-free) ----------------
__device__ __align__(16) int   g_deg[NN];
__device__ __align__(16) int   g_off[NN + 1];
__device__ __align__(16) int   g_cur[NN];
__device__ __align__(16) int   g_esrc[NE];
__device__ __align__(16) float g_ew[NE];
__device__ __align__(16) float g_Wc1[DIN * NCAT];   // [k][j] transposed+concat, layer1
__device__ __align__(16) float g_Wc2[HID * NCAT];   // layer2
__device__ __align__(16) float g_Y[(size_t)NN * NCAT];
__device__ __align__(16) float g_h1[(size_t)NN * HID];
__device__ __align__(16) float g_h2[(size_t)NN * HID];

// ---------------- packed f32x2 helpers ----------------
__device__ __forceinline__ unsigned long long pk2(float lo, float hi) {
    unsigned long long r;
    asm("mov.b64 %0, {%1,%2};" : "=l"(r) : "f"(lo), "f"(hi));
    return r;
}
__device__ __forceinline__ float2 upk2(unsigned long long v) {
    float lo, hi;
    asm("mov.b64 {%0,%1}, %2;" : "=f"(lo), "=f"(hi) : "l"(v));
    return make_float2(lo, hi);
}
__device__ __forceinline__ void ffma2(unsigned long long& c, unsigned long long a,
                                      unsigned long long b) {
    asm("fma.rn.f32x2 %0, %1, %2, %0;" : "+l"(c) : "l"(a), "l"(b));
}

// ---------------- CSR build ----------------
__global__ void k_zero_deg() {
    int i = blockIdx.x * blockDim.x + threadIdx.x;
    if (i < NN) g_deg[i] = 0;
}

__global__ void k_count(const int* __restrict__ ei) {
    int e = blockIdx.x * blockDim.x + threadIdx.x;
    if (e < NE) atomicAdd(&g_deg[ei[NE + e]], 1);
}

__global__ void k_scan() {
    __shared__ int wsum[32];
    const int tid = threadIdx.x;
    const int CH = (NN + 1023) / 1024;
    const int base = tid * CH;
    int s = 0;
    for (int i = 0; i < CH; i++) {
        int idx = base + i;
        if (idx < NN) s += g_deg[idx];
    }
    int lane = tid & 31, w = tid >> 5;
    int v = s;
    #pragma unroll
    for (int o = 1; o < 32; o <<= 1) {
        int n = __shfl_up_sync(0xffffffffu, v, o);
        if (lane >= o) v += n;
    }
    if (lane == 31) wsum[w] = v;
    __syncthreads();
    if (w == 0) {
        int x = wsum[lane];
        #pragma unroll
        for (int o = 1; o < 32; o <<= 1) {
            int n = __shfl_up_sync(0xffffffffu, x, o);
            if (lane >= o) x += n;
        }
        wsum[lane] = x;
    }
    __syncthreads();
    int excl = v - s + (w > 0 ? wsum[w - 1] : 0);
    int run = excl;
    for (int i = 0; i < CH; i++) {
        int idx = base + i;
        if (idx < NN) {
            g_off[idx] = run;
            g_cur[idx] = run;
            run += g_deg[idx];
        }
    }
    if (tid == 1023) g_off[NN] = run;
}

__global__ void k_scatter(const int* __restrict__ ei, const float* __restrict__ ea) {
    int e = blockIdx.x * blockDim.x + threadIdx.x;
    if (e < NE) {
        int d = ei[NE + e];
        int p = atomicAdd(&g_cur[d], 1);
        g_esrc[p] = ei[e];
        g_ew[p]   = ea[e];
    }
}

// ---------------- weight prep: transpose + concat into [K][256] ----------------
__global__ void k_prep_w(const float* __restrict__ Wr1, const float* __restrict__ Wro1,
                         const float* __restrict__ Wr3, const float* __restrict__ Wro3) {
    int idx = blockIdx.x * blockDim.x + threadIdx.x;
    const int n1 = DIN * NCAT;
    if (idx < n1) {
        int k = idx / NCAT, j = idx % NCAT;
        g_Wc1[idx] = (j < HID) ? Wr1[j * DIN + k] : Wro1[(j - HID) * DIN + k];
    } else if (idx < n1 + HID * NCAT) {
        int t = idx - n1;
        int k = t / NCAT, j = t % NCAT;
        g_Wc2[t] = (j < HID) ? Wr3[j * HID + k] : Wro3[(j - HID) * HID + k];
    }
}

// ---------------- fp32 SGEMM with packed FFMA2 ---------------------------------
// g_Y[M][256] = A[M][K] @ Wc[K][256]; K==96 -> A=x,B=g_Wc1 ; K==128 -> A=g_h1,B=g_Wc2
// 128x128 CTA tile, 8x8 microtile, accumulators packed as row-pairs (f32x2).
template <int K>
__global__ __launch_bounds__(256) void k_sgemm(const float* __restrict__ Ax) {
    const float* __restrict__ A = (K == 96) ? Ax : g_h1;
    const float* __restrict__ B = (K == 96) ? g_Wc1 : g_Wc2;
    __shared__ float As[8][128];
    __shared__ float Bs[8][128];
    const int tid = threadIdx.x;
    const int m0 = blockIdx.y * 128;
    const int n0 = blockIdx.x * 128;
    const int aRow = tid >> 1, aCol = (tid & 1) * 4;
    const int bRow = tid >> 5, bCol = (tid & 31) * 4;
    const int ty = tid >> 4, tx = tid & 15;

    // acc[p][j]: packed rows (ty*8+2p, ty*8+2p+1), col n0+tx*8+j
    unsigned long long acc[4][8];
    const unsigned long long z2 = pk2(0.f, 0.f);
    #pragma unroll
    for (int p = 0; p < 4; p++)
        #pragma unroll
        for (int j = 0; j < 8; j++) acc[p][j] = z2;

    for (int k0 = 0; k0 < K; k0 += 8) {
        float4 av = make_float4(0.f, 0.f, 0.f, 0.f);
        int gr = m0 + aRow;
        if (gr < NN) av = *(const float4*)(A + (size_t)gr * K + k0 + aCol);
        As[aCol + 0][aRow] = av.x;
        As[aCol + 1][aRow] = av.y;
        As[aCol + 2][aRow] = av.z;
        As[aCol + 3][aRow] = av.w;
        *(float4*)&Bs[bRow][bCol] = *(const float4*)(B + (k0 + bRow) * NCAT + n0 + bCol);
        __syncthreads();
        #pragma unroll
        for (int k = 0; k < 8; k++) {
            const float4 a0 = *(const float4*)&As[k][ty * 8];
            const float4 a1 = *(const float4*)&As[k][ty * 8 + 4];
            unsigned long long ap[4];
            ap[0] = pk2(a0.x, a0.y);
            ap[1] = pk2(a0.z, a0.w);
            ap[2] = pk2(a1.x, a1.y);
            ap[3] = pk2(a1.z, a1.w);
            const float4 b0 = *(const float4*)&Bs[k][tx * 8];
            const float4 b1 = *(const float4*)&Bs[k][tx * 8 + 4];
            unsigned long long bd[8];
            bd[0] = pk2(b0.x, b0.x); bd[1] = pk2(b0.y, b0.y);
            bd[2] = pk2(b0.z, b0.z); bd[3] = pk2(b0.w, b0.w);
            bd[4] = pk2(b1.x, b1.x); bd[5] = pk2(b1.y, b1.y);
            bd[6] = pk2(b1.z, b1.z); bd[7] = pk2(b1.w, b1.w);
            #pragma unroll
            for (int p = 0; p < 4; p++)
                #pragma unroll
                for (int j = 0; j < 8; j++)
                    ffma2(acc[p][j], ap[p], bd[j]);
        }
        __syncthreads();
    }

    // epilogue: unpack row pairs and store
    #pragma unroll
    for (int p = 0; p < 4; p++) {
        int r0 = m0 + ty * 8 + 2 * p;
        float2 u[8];
        #pragma unroll
        for (int j = 0; j < 8; j++) u[j] = upk2(acc[p][j]);
        if (r0 < NN) {
            float* d0 = g_Y + (size_t)r0 * NCAT + n0 + tx * 8;
            *(float4*)(d0)     = make_float4(u[0].x, u[1].x, u[2].x, u[3].x);
            *(float4*)(d0 + 4) = make_float4(u[4].x, u[5].x, u[6].x, u[7].x);
        }
        if (r0 + 1 < NN) {
            float* d1 = g_Y + (size_t)(r0 + 1) * NCAT + n0 + tx * 8;
            *(float4*)(d1)     = make_float4(u[0].y, u[1].y, u[2].y, u[3].y);
            *(float4*)(d1 + 4) = make_float4(u[4].y, u[5].y, u[6].y, u[7].y);
        }
    }
}

// ---------------- edge aggregation (warp per node, CSR gather, no atomics) ------
__global__ void k_agg(const float* __restrict__ bias, int layer) {
    int node = (blockIdx.x * blockDim.x + threadIdx.x) >> 5;
    if (node >= NN) return;
    int lane = threadIdx.x & 31;
    int beg = g_off[node], end = g_off[node + 1];
    float ax = 0.f, ay = 0.f, az = 0.f, aw = 0.f;
    for (int e = beg; e < end; e++) {
        int s = g_esrc[e];
        float wt = g_ew[e];
        float4 v = *(const float4*)(g_Y + (size_t)s * NCAT + 4 * lane);
        ax = fmaf(v.x, wt, ax);
        ay = fmaf(v.y, wt, ay);
        az = fmaf(v.z, wt, az);
        aw = fmaf(v.w, wt, aw);
    }
    float4 r = *(const float4*)(g_Y + (size_t)node * NCAT + HID + 4 * lane);
    float4 b = *(const float4*)(bias + 4 * lane);
    ax += r.x + b.x;
    ay += r.y + b.y;
    az += r.z + b.z;
    aw += r.w + b.w;
    float* H;
    if (layer == 1) {
        ax = fmaxf(ax, 0.f); ay = fmaxf(ay, 0.f);
        az = fmaxf(az, 0.f); aw = fmaxf(aw, 0.f);
        H = g_h1;
    } else {
        H = g_h2;
    }
    *(float4*)(H + (size_t)node * HID + 4 * lane) = make_float4(ax, ay, az, aw);
}

// ---------------- pooling + head (batch sorted -> binary search) ----------------
__global__ void k_pool(const int* __restrict__ batch, const float* __restrict__ Wl,
                       const float* __restrict__ bl, float* __restrict__ out) {
    int g = blockIdx.x;
    int c = threadIdx.x;  // 128 threads
    int lo = 0, hi = NN;
    while (lo < hi) {
        int m = (lo + hi) >> 1;
        if (batch[m] < g) lo = m + 1; else hi = m;
    }
    int l = lo, h = NN;
    while (l < h) {
        int m = (l + h) >> 1;
        if (batch[m] < g + 1) l = m + 1; else h = m;
    }
    int cnt = l - lo;
    float s = 0.f;
    for (int i = lo; i < l; i++) s += g_h2[(size_t)i * HID + c];
    float p = s / fmaxf((float)cnt, 1.f);
    float v = p * Wl[c];
    __shared__ float red[128];
    red[c] = v;
    __syncthreads();
    for (int st = 64; st > 0; st >>= 1) {
        if (c < st) red[c] += red[c + st];
        __syncthreads();
    }
    if (c == 0) out[g] = fmaxf(red[0] + bl[0], 0.f);
}

// ---------------- launch ----------------
extern "C" void kernel_launch(void* const* d_in, const int* in_sizes, int n_in,
                              void* d_out, int out_size) {
    const float* x     = (const float*)d_in[0];
    const int*   ei    = (const int*)d_in[1];
    const int*   batch = (const int*)d_in[2];
    const float* ea    = (const float*)d_in[3];
    const float* Wr1   = (const float*)d_in[4];
    const float* b1    = (const float*)d_in[5];
    const float* Wro1  = (const float*)d_in[6];
    const float* Wr3   = (const float*)d_in[7];
    const float* b3    = (const float*)d_in[8];
    const float* Wro3  = (const float*)d_in[9];
    const float* Wl    = (const float*)d_in[10];
    const float* bl    = (const float*)d_in[11];
    float* out = (float*)d_out;

    k_zero_deg<<<(NN + 255) / 256, 256>>>();
    k_count<<<(NE + 255) / 256, 256>>>(ei);
    k_scan<<<1, 1024>>>();
    k_scatter<<<(NE + 255) / 256, 256>>>(ei, ea);
    k_prep_w<<<((DIN + HID) * NCAT + 255) / 256, 256>>>(Wr1, Wro1, Wr3, Wro3);

    dim3 ggrid(2, (NN + 127) / 128);
    // layer 1
    k_sgemm<96><<<ggrid, 256>>>(x);
    k_agg<<<(NN * 32 + 255) / 256, 256>>>(b1, 1);
    // layer 2
    k_sgemm<128><<<ggrid, 256>>>(nullptr);
    k_agg<<<(NN * 32 + 255) / 256, 256>>>(b3, 2);
    // pool + head
    k_pool<<<NG, 128>>>(batch, Wl, bl, out);
}

// round 5
// speedup vs baseline: 8.7293x; 1.0398x over previous
#include <cuda_runtime.h>
#include <cuda_fp16.h>

#define NN 50000
#define NE 800000
#define DIN 96
#define HID 128
#define NG 256
#define NCAT 256   // [W_rel | W_root] concatenated output width

// ---------------- scratch (__device__ globals; allocation-free) ----------------
__device__ __align__(16) int    g_deg[NN];
__device__ __align__(16) int    g_off[NN + 1];
__device__ __align__(16) int    g_cur[NN];
__device__ __align__(16) int2   g_edge[NE];          // (src, w-as-int)
__device__ __align__(16) float  g_Wc1[DIN * NCAT];
__device__ __align__(16) float  g_Wc2[HID * NCAT];
__device__ __align__(16) __half g_Yr16[(size_t)NN * HID];  // rel half, fp16 (gathered)
__device__ __align__(16) float  g_Yroot[(size_t)NN * HID]; // root half, fp32
__device__ __align__(16) float  g_h1[(size_t)NN * HID];
__device__ __align__(16) float  g_h2[(size_t)NN * HID];

// ---------------- packed f32x2 helpers ----------------
__device__ __forceinline__ unsigned long long pk2(float lo, float hi) {
    unsigned long long r;
    asm("mov.b64 %0, {%1,%2};" : "=l"(r) : "f"(lo), "f"(hi));
    return r;
}
__device__ __forceinline__ float2 upk2(unsigned long long v) {
    float lo, hi;
    asm("mov.b64 {%0,%1}, %2;" : "=f"(lo), "=f"(hi) : "l"(v));
    return make_float2(lo, hi);
}
__device__ __forceinline__ void ffma2(unsigned long long& c, unsigned long long a,
                                      unsigned long long b) {
    asm("fma.rn.f32x2 %0, %1, %2, %0;" : "+l"(c) : "l"(a), "l"(b));
}

// ---------------- CSR build ----------------
__global__ void k_zero_deg() {
    int i = blockIdx.x * blockDim.x + threadIdx.x;
    if (i < NN) g_deg[i] = 0;
}

__global__ void k_count(const int* __restrict__ ei) {
    int e = blockIdx.x * blockDim.x + threadIdx.x;
    if (e < NE) atomicAdd(&g_deg[ei[NE + e]], 1);
}

__global__ void k_scan() {
    __shared__ int wsum[32];
    const int tid = threadIdx.x;
    const int CH = (NN + 1023) / 1024;
    const int base = tid * CH;
    int s = 0;
    for (int i = 0; i < CH; i++) {
        int idx = base + i;
        if (idx < NN) s += g_deg[idx];
    }
    int lane = tid & 31, w = tid >> 5;
    int v = s;
    #pragma unroll
    for (int o = 1; o < 32; o <<= 1) {
        int n = __shfl_up_sync(0xffffffffu, v, o);
        if (lane >= o) v += n;
    }
    if (lane == 31) wsum[w] = v;
    __syncthreads();
    if (w == 0) {
        int x = wsum[lane];
        #pragma unroll
        for (int o = 1; o < 32; o <<= 1) {
            int n = __shfl_up_sync(0xffffffffu, x, o);
            if (lane >= o) x += n;
        }
        wsum[lane] = x;
    }
    __syncthreads();
    int excl = v - s + (w > 0 ? wsum[w - 1] : 0);
    int run = excl;
    for (int i = 0; i < CH; i++) {
        int idx = base + i;
        if (idx < NN) {
            g_off[idx] = run;
            g_cur[idx] = run;
            run += g_deg[idx];
        }
    }
    if (tid == 1023) g_off[NN] = run;
}

__global__ void k_scatter(const int* __restrict__ ei, const float* __restrict__ ea) {
    int e = blockIdx.x * blockDim.x + threadIdx.x;
    if (e < NE) {
        int d = ei[NE + e];
        int p = atomicAdd(&g_cur[d], 1);
        g_edge[p] = make_int2(ei[e], __float_as_int(ea[e]));
    }
}

// ---------------- weight prep: transpose + concat into [K][256] ----------------
__global__ void k_prep_w(const float* __restrict__ Wr1, const float* __restrict__ Wro1,
                         const float* __restrict__ Wr3, const float* __restrict__ Wro3) {
    int idx = blockIdx.x * blockDim.x + threadIdx.x;
    const int n1 = DIN * NCAT;
    if (idx < n1) {
        int k = idx / NCAT, j = idx % NCAT;
        g_Wc1[idx] = (j < HID) ? Wr1[j * DIN + k] : Wro1[(j - HID) * DIN + k];
    } else if (idx < n1 + HID * NCAT) {
        int t = idx - n1;
        int k = t / NCAT, j = t % NCAT;
        g_Wc2[t] = (j < HID) ? Wr3[j * HID + k] : Wro3[(j - HID) * HID + k];
    }
}

// ---------------- fp32 SGEMM (packed FFMA2), split fp16/fp32 epilogue ----------
// blockIdx.x==0 -> rel cols 0..127 -> g_Yr16 (fp16); ==1 -> root cols -> g_Yroot fp32
template <int K>
__global__ __launch_bounds__(256) void k_sgemm(const float* __restrict__ Ax) {
    const float* __restrict__ A = (K == 96) ? Ax : g_h1;
    const float* __restrict__ B = (K == 96) ? g_Wc1 : g_Wc2;
    __shared__ float As[8][128];
    __shared__ float Bs[8][128];
    const int tid = threadIdx.x;
    const int m0 = blockIdx.y * 128;
    const int n0 = blockIdx.x * 128;
    const int aRow = tid >> 1, aCol = (tid & 1) * 4;
    const int bRow = tid >> 5, bCol = (tid & 31) * 4;
    const int ty = tid >> 4, tx = tid & 15;

    unsigned long long acc[4][8];
    const unsigned long long z2 = pk2(0.f, 0.f);
    #pragma unroll
    for (int p = 0; p < 4; p++)
        #pragma unroll
        for (int j = 0; j < 8; j++) acc[p][j] = z2;

    for (int k0 = 0; k0 < K; k0 += 8) {
        float4 av = make_float4(0.f, 0.f, 0.f, 0.f);
        int gr = m0 + aRow;
        if (gr < NN) av = *(const float4*)(A + (size_t)gr * K + k0 + aCol);
        As[aCol + 0][aRow] = av.x;
        As[aCol + 1][aRow] = av.y;
        As[aCol + 2][aRow] = av.z;
        As[aCol + 3][aRow] = av.w;
        *(float4*)&Bs[bRow][bCol] = *(const float4*)(B + (k0 + bRow) * NCAT + n0 + bCol);
        __syncthreads();
        #pragma unroll
        for (int k = 0; k < 8; k++) {
            const float4 a0 = *(const float4*)&As[k][ty * 8];
            const float4 a1 = *(const float4*)&As[k][ty * 8 + 4];
            unsigned long long ap[4];
            ap[0] = pk2(a0.x, a0.y);
            ap[1] = pk2(a0.z, a0.w);
            ap[2] = pk2(a1.x, a1.y);
            ap[3] = pk2(a1.z, a1.w);
            const float4 b0 = *(const float4*)&Bs[k][tx * 8];
            const float4 b1 = *(const float4*)&Bs[k][tx * 8 + 4];
            unsigned long long bd[8];
            bd[0] = pk2(b0.x, b0.x); bd[1] = pk2(b0.y, b0.y);
            bd[2] = pk2(b0.z, b0.z); bd[3] = pk2(b0.w, b0.w);
            bd[4] = pk2(b1.x, b1.x); bd[5] = pk2(b1.y, b1.y);
            bd[6] = pk2(b1.z, b1.z); bd[7] = pk2(b1.w, b1.w);
            #pragma unroll
            for (int p = 0; p < 4; p++)
                #pragma unroll
                for (int j = 0; j < 8; j++)
                    ffma2(acc[p][j], ap[p], bd[j]);
        }
        __syncthreads();
    }

    const bool relPart = (blockIdx.x == 0);
    #pragma unroll
    for (int p = 0; p < 4; p++) {
        int r0 = m0 + ty * 8 + 2 * p;
        float2 u[8];
        #pragma unroll
        for (int j = 0; j < 8; j++) u[j] = upk2(acc[p][j]);
        if (relPart) {
            // fp16 store: row-major [NN][128], 8 halves = 16B per row
            if (r0 < NN) {
                __half2 h0 = __floats2half2_rn(u[0].x, u[1].x);
                __half2 h1 = __floats2half2_rn(u[2].x, u[3].x);
                __half2 h2 = __floats2half2_rn(u[4].x, u[5].x);
                __half2 h3 = __floats2half2_rn(u[6].x, u[7].x);
                uint4 v;
                v.x = *(unsigned*)&h0; v.y = *(unsigned*)&h1;
                v.z = *(unsigned*)&h2; v.w = *(unsigned*)&h3;
                *(uint4*)(g_Yr16 + (size_t)r0 * HID + tx * 8) = v;
            }
            if (r0 + 1 < NN) {
                __half2 h0 = __floats2half2_rn(u[0].y, u[1].y);
                __half2 h1 = __floats2half2_rn(u[2].y, u[3].y);
                __half2 h2 = __floats2half2_rn(u[4].y, u[5].y);
                __half2 h3 = __floats2half2_rn(u[6].y, u[7].y);
                uint4 v;
                v.x = *(unsigned*)&h0; v.y = *(unsigned*)&h1;
                v.z = *(unsigned*)&h2; v.w = *(unsigned*)&h3;
                *(uint4*)(g_Yr16 + (size_t)(r0 + 1) * HID + tx * 8) = v;
            }
        } else {
            if (r0 < NN) {
                float* d0 = g_Yroot + (size_t)r0 * HID + tx * 8;
                *(float4*)(d0)     = make_float4(u[0].x, u[1].x, u[2].x, u[3].x);
                *(float4*)(d0 + 4) = make_float4(u[4].x, u[5].x, u[6].x, u[7].x);
            }
            if (r0 + 1 < NN) {
                float* d1 = g_Yroot + (size_t)(r0 + 1) * HID + tx * 8;
                *(float4*)(d1)     = make_float4(u[0].y, u[1].y, u[2].y, u[3].y);
                *(float4*)(d1 + 4) = make_float4(u[4].y, u[5].y, u[6].y, u[7].y);
            }
        }
    }
}

// ---------------- edge aggregation: fp16 gather, warp per node -----------------
__global__ void k_agg(const float* __restrict__ bias, int layer) {
    int node = (blockIdx.x * blockDim.x + threadIdx.x) >> 5;
    if (node >= NN) return;
    int lane = threadIdx.x & 31;
    int beg = g_off[node], end = g_off[node + 1];
    float ax = 0.f, ay = 0.f, az = 0.f, aw = 0.f;
    float bx = 0.f, by = 0.f, bz = 0.f, bw = 0.f;
    int e = beg;
    for (; e + 1 < end; e += 2) {
        int2 e0 = g_edge[e];
        int2 e1 = g_edge[e + 1];
        uint2 v0 = *(const uint2*)(g_Yr16 + (size_t)e0.x * HID + 4 * lane);
        uint2 v1 = *(const uint2*)(g_Yr16 + (size_t)e1.x * HID + 4 * lane);
        float w0 = __int_as_float(e0.y);
        float w1 = __int_as_float(e1.y);
        float2 p00 = __half22float2(*(__half2*)&v0.x);
        float2 p01 = __half22float2(*(__half2*)&v0.y);
        float2 p10 = __half22float2(*(__half2*)&v1.x);
        float2 p11 = __half22float2(*(__half2*)&v1.y);
        ax = fmaf(p00.x, w0, ax); ay = fmaf(p00.y, w0, ay);
        az = fmaf(p01.x, w0, az); aw = fmaf(p01.y, w0, aw);
        bx = fmaf(p10.x, w1, bx); by = fmaf(p10.y, w1, by);
        bz = fmaf(p11.x, w1, bz); bw = fmaf(p11.y, w1, bw);
    }
    if (e < end) {
        int2 e0 = g_edge[e];
        uint2 v0 = *(const uint2*)(g_Yr16 + (size_t)e0.x * HID + 4 * lane);
        float w0 = __int_as_float(e0.y);
        float2 p00 = __half22float2(*(__half2*)&v0.x);
        float2 p01 = __half22float2(*(__half2*)&v0.y);
        ax = fmaf(p00.x, w0, ax); ay = fmaf(p00.y, w0, ay);
        az = fmaf(p01.x, w0, az); aw = fmaf(p01.y, w0, aw);
    }
    ax += bx; ay += by; az += bz; aw += bw;
    float4 r = *(const float4*)(g_Yroot + (size_t)node * HID + 4 * lane);
    float4 b = *(const float4*)(bias + 4 * lane);
    ax += r.x + b.x;
    ay += r.y + b.y;
    az += r.z + b.z;
    aw += r.w + b.w;
    float* H;
    if (layer == 1) {
        ax = fmaxf(ax, 0.f); ay = fmaxf(ay, 0.f);
        az = fmaxf(az, 0.f); aw = fmaxf(aw, 0.f);
        H = g_h1;
    } else {
        H = g_h2;
    }
    *(float4*)(H + (size_t)node * HID + 4 * lane) = make_float4(ax, ay, az, aw);
}

// ---------------- pooling + head (batch sorted -> binary search) ----------------
__global__ void k_pool(const int* __restrict__ batch, const float* __restrict__ Wl,
                       const float* __restrict__ bl, float* __restrict__ out) {
    int g = blockIdx.x;
    int c = threadIdx.x;
    int lo = 0, hi = NN;
    while (lo < hi) {
        int m = (lo + hi) >> 1;
        if (batch[m] < g) lo = m + 1; else hi = m;
    }
    int l = lo, h = NN;
    while (l < h) {
        int m = (l + h) >> 1;
        if (batch[m] < g + 1) l = m + 1; else h = m;
    }
    int cnt = l - lo;
    float s = 0.f;
    for (int i = lo; i < l; i++) s += g_h2[(size_t)i * HID + c];
    float p = s / fmaxf((float)cnt, 1.f);
    float v = p * Wl[c];
    __shared__ float red[128];
    red[c] = v;
    __syncthreads();
    for (int st = 64; st > 0; st >>= 1) {
        if (c < st) red[c] += red[c + st];
        __syncthreads();
    }
    if (c == 0) out[g] = fmaxf(red[0] + bl[0], 0.f);
}

// ---------------- launch ----------------
extern "C" void kernel_launch(void* const* d_in, const int* in_sizes, int n_in,
                              void* d_out, int out_size) {
    const float* x     = (const float*)d_in[0];
    const int*   ei    = (const int*)d_in[1];
    const int*   batch = (const int*)d_in[2];
    const float* ea    = (const float*)d_in[3];
    const float* Wr1   = (const float*)d_in[4];
    const float* b1    = (const float*)d_in[5];
    const float* Wro1  = (const float*)d_in[6];
    const float* Wr3   = (const float*)d_in[7];
    const float* b3    = (const float*)d_in[8];
    const float* Wro3  = (const float*)d_in[9];
    const float* Wl    = (const float*)d_in[10];
    const float* bl    = (const float*)d_in[11];
    float* out = (float*)d_out;

    k_zero_deg<<<(NN + 255) / 256, 256>>>();
    k_count<<<(NE + 255) / 256, 256>>>(ei);
    k_scan<<<1, 1024>>>();
    k_scatter<<<(NE + 255) / 256, 256>>>(ei, ea);
    k_prep_w<<<((DIN + HID) * NCAT + 255) / 256, 256>>>(Wr1, Wro1, Wr3, Wro3);

    dim3 ggrid(2, (NN + 127) / 128);
    // layer 1
    k_sgemm<96><<<ggrid, 256>>>(x);
    k_agg<<<(NN * 32 + 255) / 256, 256>>>(b1, 1);
    // layer 2
    k_sgemm<128><<<ggrid, 256>>>(nullptr);
    k_agg<<<(NN * 32 + 255) / 256, 256>>>(b3, 2);
    // pool + head
    k_pool<<<NG, 128>>>(batch, Wl, bl, out);
}

// round 6
// speedup vs baseline: 8.9482x; 1.0251x over previous
#include <cuda_runtime.h>
#include <cuda_fp16.h>

#define NN 50000
#define NE 800000
#define DIN 96
#define HID 128
#define NG 256
#define NCAT 256   // [W_rel | W_root] concatenated output width

// ---------------- scratch (__device__ globals; allocation-free) ----------------
__device__ __align__(16) int    g_deg[NN];
__device__ __align__(16) int    g_off[NN + 1];
__device__ __align__(16) int    g_cur[NN];
__device__ __align__(16) int2   g_edge[NE];          // (src, w-as-int)
__device__ __align__(16) float  g_Wc1[DIN * NCAT];
__device__ __align__(16) float  g_Wc2[HID * NCAT];
__device__ __align__(16) __half g_Yr16[(size_t)NN * HID];  // rel half, fp16 (gathered)
__device__ __align__(16) float  g_Yroot[(size_t)NN * HID]; // root half, fp32
__device__ __align__(16) float  g_h1[(size_t)NN * HID];
__device__ __align__(16) float  g_h2[(size_t)NN * HID];

// ---------------- CSR build ----------------
__global__ void k_zero_deg() {
    int i = blockIdx.x * blockDim.x + threadIdx.x;
    if (i < NN) g_deg[i] = 0;
}

__global__ void k_count(const int* __restrict__ ei) {
    int e = blockIdx.x * blockDim.x + threadIdx.x;
    if (e < NE) atomicAdd(&g_deg[ei[NE + e]], 1);
}

__global__ void k_scan() {
    __shared__ int wsum[32];
    const int tid = threadIdx.x;
    const int CH = (NN + 1023) / 1024;
    const int base = tid * CH;
    int s = 0;
    for (int i = 0; i < CH; i++) {
        int idx = base + i;
        if (idx < NN) s += g_deg[idx];
    }
    int lane = tid & 31, w = tid >> 5;
    int v = s;
    #pragma unroll
    for (int o = 1; o < 32; o <<= 1) {
        int n = __shfl_up_sync(0xffffffffu, v, o);
        if (lane >= o) v += n;
    }
    if (lane == 31) wsum[w] = v;
    __syncthreads();
    if (w == 0) {
        int x = wsum[lane];
        #pragma unroll
        for (int o = 1; o < 32; o <<= 1) {
            int n = __shfl_up_sync(0xffffffffu, x, o);
            if (lane >= o) x += n;
        }
        wsum[lane] = x;
    }
    __syncthreads();
    int excl = v - s + (w > 0 ? wsum[w - 1] : 0);
    int run = excl;
    for (int i = 0; i < CH; i++) {
        int idx = base + i;
        if (idx < NN) {
            g_off[idx] = run;
            g_cur[idx] = run;
            run += g_deg[idx];
        }
    }
    if (tid == 1023) g_off[NN] = run;
}

__global__ void k_scatter(const int* __restrict__ ei, const float* __restrict__ ea) {
    int e = blockIdx.x * blockDim.x + threadIdx.x;
    if (e < NE) {
        int d = ei[NE + e];
        int p = atomicAdd(&g_cur[d], 1);
        g_edge[p] = make_int2(ei[e], __float_as_int(ea[e]));
    }
}

// ---------------- weight prep: transpose + concat into [K][256] ----------------
__global__ void k_prep_w(const float* __restrict__ Wr1, const float* __restrict__ Wro1,
                         const float* __restrict__ Wr3, const float* __restrict__ Wro3) {
    int idx = blockIdx.x * blockDim.x + threadIdx.x;
    const int n1 = DIN * NCAT;
    if (idx < n1) {
        int k = idx / NCAT, j = idx % NCAT;
        g_Wc1[idx] = (j < HID) ? Wr1[j * DIN + k] : Wro1[(j - HID) * DIN + k];
    } else if (idx < n1 + HID * NCAT) {
        int t = idx - n1;
        int k = t / NCAT, j = t % NCAT;
        g_Wc2[t] = (j < HID) ? Wr3[j * HID + k] : Wro3[(j - HID) * HID + k];
    }
}

// ---------------- fp32 SGEMM: double-buffered, BK=16, reg-prefetch -------------
// g_Y*[M][128] per n-half = A[M][K] @ Wc[K][256] slice.
// blockIdx.x==0 -> rel cols -> g_Yr16 (fp16); ==1 -> root cols -> g_Yroot (fp32)
template <int K>
__global__ __launch_bounds__(256) void k_sgemm(const float* __restrict__ Ax) {
    const float* __restrict__ A = (K == 96) ? Ax : g_h1;
    const float* __restrict__ B = (K == 96) ? g_Wc1 : g_Wc2;
    __shared__ float As[2][16][128];
    __shared__ float Bs[2][16][128];
    const int tid = threadIdx.x;
    const int m0 = blockIdx.y * 128;
    const int n0 = blockIdx.x * 128;
    const int ty = tid >> 4, tx = tid & 15;
    const int NI = K / 16;

    // global-load index mapping (2 float4 per thread per operand per iteration)
    const int aR0 = tid >> 2, aC0 = (tid & 3) * 4;           // +256: rows 64..127
    const int bK0 = tid >> 5, bN0 = (tid & 31) * 4;          // +256: k 8..15

    float4 pa[2], pb[2];
    auto ldA = [&](int k0) {
        #pragma unroll
        for (int i = 0; i < 2; i++) {
            int r = aR0 + i * 64;
            int gr = m0 + r;
            pa[i] = (gr < NN) ? *(const float4*)(A + (size_t)gr * K + k0 + aC0)
                              : make_float4(0.f, 0.f, 0.f, 0.f);
        }
    };
    auto ldB = [&](int k0) {
        #pragma unroll
        for (int i = 0; i < 2; i++) {
            int kk = bK0 + i * 8;
            pb[i] = *(const float4*)(B + (size_t)(k0 + kk) * NCAT + n0 + bN0);
        }
    };
    auto stAB = [&](int buf) {
        #pragma unroll
        for (int i = 0; i < 2; i++) {
            int r = aR0 + i * 64;
            As[buf][aC0 + 0][r] = pa[i].x;
            As[buf][aC0 + 1][r] = pa[i].y;
            As[buf][aC0 + 2][r] = pa[i].z;
            As[buf][aC0 + 3][r] = pa[i].w;
            *(float4*)&Bs[buf][bK0 + i * 8][bN0] = pb[i];
        }
    };

    float acc[8][8];
    #pragma unroll
    for (int i = 0; i < 8; i++)
        #pragma unroll
        for (int j = 0; j < 8; j++) acc[i][j] = 0.f;

    ldA(0); ldB(0);
    stAB(0);
    __syncthreads();

    int buf = 0;
    for (int it = 0; it < NI; it++) {
        if (it + 1 < NI) { ldA((it + 1) * 16); ldB((it + 1) * 16); }
        #pragma unroll
        for (int k = 0; k < 16; k++) {
            const float4 a0 = *(const float4*)&As[buf][k][ty * 8];
            const float4 a1 = *(const float4*)&As[buf][k][ty * 8 + 4];
            const float4 b0 = *(const float4*)&Bs[buf][k][tx * 8];
            const float4 b1 = *(const float4*)&Bs[buf][k][tx * 8 + 4];
            const float ar[8] = {a0.x, a0.y, a0.z, a0.w, a1.x, a1.y, a1.z, a1.w};
            const float br[8] = {b0.x, b0.y, b0.z, b0.w, b1.x, b1.y, b1.z, b1.w};
            #pragma unroll
            for (int i = 0; i < 8; i++)
                #pragma unroll
                for (int j = 0; j < 8; j++)
                    acc[i][j] = fmaf(ar[i], br[j], acc[i][j]);
        }
        if (it + 1 < NI) stAB(buf ^ 1);
        __syncthreads();
        buf ^= 1;
    }

    const bool relPart = (blockIdx.x == 0);
    #pragma unroll
    for (int i = 0; i < 8; i++) {
        int r = m0 + ty * 8 + i;
        if (r >= NN) continue;
        if (relPart) {
            __half2 h0 = __floats2half2_rn(acc[i][0], acc[i][1]);
            __half2 h1 = __floats2half2_rn(acc[i][2], acc[i][3]);
            __half2 h2 = __floats2half2_rn(acc[i][4], acc[i][5]);
            __half2 h3 = __floats2half2_rn(acc[i][6], acc[i][7]);
            uint4 v;
            v.x = *(unsigned*)&h0; v.y = *(unsigned*)&h1;
            v.z = *(unsigned*)&h2; v.w = *(unsigned*)&h3;
            *(uint4*)(g_Yr16 + (size_t)r * HID + tx * 8) = v;
        } else {
            float* d0 = g_Yroot + (size_t)r * HID + tx * 8;
            *(float4*)(d0)     = make_float4(acc[i][0], acc[i][1], acc[i][2], acc[i][3]);
            *(float4*)(d0 + 4) = make_float4(acc[i][4], acc[i][5], acc[i][6], acc[i][7]);
        }
    }
}

// ---------------- edge aggregation: fp16 gather, warp per node -----------------
__global__ void k_agg(const float* __restrict__ bias, int layer) {
    int node = (blockIdx.x * blockDim.x + threadIdx.x) >> 5;
    if (node >= NN) return;
    int lane = threadIdx.x & 31;
    int beg = g_off[node], end = g_off[node + 1];
    float ax = 0.f, ay = 0.f, az = 0.f, aw = 0.f;
    float bx = 0.f, by = 0.f, bz = 0.f, bw = 0.f;
    int e = beg;
    for (; e + 1 < end; e += 2) {
        int2 e0 = g_edge[e];
        int2 e1 = g_edge[e + 1];
        uint2 v0 = *(const uint2*)(g_Yr16 + (size_t)e0.x * HID + 4 * lane);
        uint2 v1 = *(const uint2*)(g_Yr16 + (size_t)e1.x * HID + 4 * lane);
        float w0 = __int_as_float(e0.y);
        float w1 = __int_as_float(e1.y);
        float2 p00 = __half22float2(*(__half2*)&v0.x);
        float2 p01 = __half22float2(*(__half2*)&v0.y);
        float2 p10 = __half22float2(*(__half2*)&v1.x);
        float2 p11 = __half22float2(*(__half2*)&v1.y);
        ax = fmaf(p00.x, w0, ax); ay = fmaf(p00.y, w0, ay);
        az = fmaf(p01.x, w0, az); aw = fmaf(p01.y, w0, aw);
        bx = fmaf(p10.x, w1, bx); by = fmaf(p10.y, w1, by);
        bz = fmaf(p11.x, w1, bz); bw = fmaf(p11.y, w1, bw);
    }
    if (e < end) {
        int2 e0 = g_edge[e];
        uint2 v0 = *(const uint2*)(g_Yr16 + (size_t)e0.x * HID + 4 * lane);
        float w0 = __int_as_float(e0.y);
        float2 p00 = __half22float2(*(__half2*)&v0.x);
        float2 p01 = __half22float2(*(__half2*)&v0.y);
        ax = fmaf(p00.x, w0, ax); ay = fmaf(p00.y, w0, ay);
        az = fmaf(p01.x, w0, az); aw = fmaf(p01.y, w0, aw);
    }
    ax += bx; ay += by; az += bz; aw += bw;
    float4 r = *(const float4*)(g_Yroot + (size_t)node * HID + 4 * lane);
    float4 b = *(const float4*)(bias + 4 * lane);
    ax += r.x + b.x;
    ay += r.y + b.y;
    az += r.z + b.z;
    aw += r.w + b.w;
    float* H;
    if (layer == 1) {
        ax = fmaxf(ax, 0.f); ay = fmaxf(ay, 0.f);
        az = fmaxf(az, 0.f); aw = fmaxf(aw, 0.f);
        H = g_h1;
    } else {
        H = g_h2;
    }
    *(float4*)(H + (size_t)node * HID + 4 * lane) = make_float4(ax, ay, az, aw);
}

// ---------------- pooling + head (batch sorted -> binary search) ----------------
__global__ void k_pool(const int* __restrict__ batch, const float* __restrict__ Wl,
                       const float* __restrict__ bl, float* __restrict__ out) {
    int g = blockIdx.x;
    int c = threadIdx.x;
    int lo = 0, hi = NN;
    while (lo < hi) {
        int m = (lo + hi) >> 1;
        if (batch[m] < g) lo = m + 1; else hi = m;
    }
    int l = lo, h = NN;
    while (l < h) {
        int m = (l + h) >> 1;
        if (batch[m] < g + 1) l = m + 1; else h = m;
    }
    int cnt = l - lo;
    float s = 0.f;
    for (int i = lo; i < l; i++) s += g_h2[(size_t)i * HID + c];
    float p = s / fmaxf((float)cnt, 1.f);
    float v = p * Wl[c];
    __shared__ float red[128];
    red[c] = v;
    __syncthreads();
    for (int st = 64; st > 0; st >>= 1) {
        if (c < st) red[c] += red[c + st];
        __syncthreads();
    }
    if (c == 0) out[g] = fmaxf(red[0] + bl[0], 0.f);
}

// ---------------- launch ----------------
extern "C" void kernel_launch(void* const* d_in, const int* in_sizes, int n_in,
                              void* d_out, int out_size) {
    const float* x     = (const float*)d_in[0];
    const int*   ei    = (const int*)d_in[1];
    const int*   batch = (const int*)d_in[2];
    const float* ea    = (const float*)d_in[3];
    const float* Wr1   = (const float*)d_in[4];
    const float* b1    = (const float*)d_in[5];
    const float* Wro1  = (const float*)d_in[6];
    const float* Wr3   = (const float*)d_in[7];
    const float* b3    = (const float*)d_in[8];
    const float* Wro3  = (const float*)d_in[9];
    const float* Wl    = (const float*)d_in[10];
    const float* bl    = (const float*)d_in[11];
    float* out = (float*)d_out;

    k_zero_deg<<<(NN + 255) / 256, 256>>>();
    k_count<<<(NE + 255) / 256, 256>>>(ei);
    k_scan<<<1, 1024>>>();
    k_scatter<<<(NE + 255) / 256, 256>>>(ei, ea);
    k_prep_w<<<((DIN + HID) * NCAT + 255) / 256, 256>>>(Wr1, Wro1, Wr3, Wro3);

    dim3 ggrid(2, (NN + 127) / 128);
    // layer 1
    k_sgemm<96><<<ggrid, 256>>>(x);
    k_agg<<<(NN * 32 + 255) / 256, 256>>>(b1, 1);
    // layer 2
    k_sgemm<128><<<ggrid, 256>>>(nullptr);
    k_agg<<<(NN * 32 + 255) / 256, 256>>>(b3, 2);
    // pool + head
    k_pool<<<NG, 128>>>(batch, Wl, bl, out);
}